// round 12
// baseline (speedup 1.0000x reference)
#include <cuda_runtime.h>
#include <cuda_bf16.h>
#include <cstdint>

// 12-bit adder over float-encoded bits. Bit 11 = LSB.
// Output: sums [BATCH,12] then carry [BATCH,1], float32.
//
// R8: smem-staged, fully-coalesced global access. 48B/thread row stride
// made every LDG/STG.128 wavefront span 12 lines; staging through smem
// makes all global traffic unit-stride (4 lines/wavefront). Row reads
// from smem at word-stride 12 are bank-conflict-free for LDS.128.
// Integer-only bit path (bit 23 of 0x3F800000) — no F2I/I2F.

#define ROWS_PER_BLOCK 256
#define VEC_PER_BLOCK  (ROWS_PER_BLOCK * 3)   // 768 uint4

__device__ __forceinline__ uint32_t pack12(uint4 u0, uint4 u1, uint4 u2)
{
    return ((u0.x >> 12) & 0x800u) | ((u0.y >> 13) & 0x400u) |
           ((u0.z >> 14) & 0x200u) | ((u0.w >> 15) & 0x100u) |
           ((u1.x >> 16) & 0x080u) | ((u1.y >> 17) & 0x040u) |
           ((u1.z >> 18) & 0x020u) | ((u1.w >> 19) & 0x010u) |
           ((u2.x >> 20) & 0x008u) | ((u2.y >> 21) & 0x004u) |
           ((u2.z >> 22) & 0x002u) | ((u2.w >> 23) & 0x001u);
}

__device__ __forceinline__ uint32_t fbit(uint32_t s, int p)
{
    return ((s >> p) & 1u) * 0x3F800000u;   // 0.0f or 1.0f as raw bits
}

__global__ __launch_bounds__(ROWS_PER_BLOCK) void adder12_kernel(
    const uint4* __restrict__ A4,
    const uint4* __restrict__ B4,
    uint4* __restrict__ S4,
    uint32_t* __restrict__ Cout)
{
    __shared__ uint4 smA[VEC_PER_BLOCK];   // A staging, reused for sums
    __shared__ uint4 smB[VEC_PER_BLOCK];

    const int tid = threadIdx.x;
    const size_t blk_base = (size_t)blockIdx.x * VEC_PER_BLOCK;

    // Stage 1: fully coalesced global -> smem (unit stride across lanes).
#pragma unroll
    for (int i = 0; i < 3; i++) {
        smA[tid + i * ROWS_PER_BLOCK] = A4[blk_base + tid + i * ROWS_PER_BLOCK];
        smB[tid + i * ROWS_PER_BLOCK] = B4[blk_base + tid + i * ROWS_PER_BLOCK];
    }
    __syncthreads();

    // Stage 2: per-row compute from smem (stride-12-word LDS: conflict-free).
    {
        const int rb = 3 * tid;
        uint4 a0 = smA[rb + 0], a1 = smA[rb + 1], a2 = smA[rb + 2];
        uint4 b0 = smB[rb + 0], b1 = smB[rb + 1], b2 = smB[rb + 2];

        uint32_t s = pack12(a0, a1, a2) + pack12(b0, b1, b2);

        uint4 o;
        o.x = fbit(s, 11); o.y = fbit(s, 10); o.z = fbit(s, 9);  o.w = fbit(s, 8);
        smA[rb + 0] = o;
        o.x = fbit(s, 7);  o.y = fbit(s, 6);  o.z = fbit(s, 5);  o.w = fbit(s, 4);
        smA[rb + 1] = o;
        o.x = fbit(s, 3);  o.y = fbit(s, 2);  o.z = fbit(s, 1);  o.w = fbit(s, 0);
        smA[rb + 2] = o;

        Cout[blockIdx.x * ROWS_PER_BLOCK + tid] = fbit(s, 12);  // unit stride
    }
    __syncthreads();

    // Stage 3: fully coalesced smem -> global stores.
#pragma unroll
    for (int i = 0; i < 3; i++) {
        S4[blk_base + tid + i * ROWS_PER_BLOCK] = smA[tid + i * ROWS_PER_BLOCK];
    }
}

extern "C" void kernel_launch(void* const* d_in, const int* in_sizes, int n_in,
                              void* d_out, int out_size)
{
    const uint4* A4 = (const uint4*)d_in[0];
    const uint4* B4 = (const uint4*)d_in[1];
    float* out = (float*)d_out;

    const int n_rows = in_sizes[0] / 12;                 // 4194304
    const int blocks = n_rows / ROWS_PER_BLOCK;          // 16384 (exact)

    uint4* S4 = (uint4*)out;
    uint32_t* Cout = (uint32_t*)(out + (size_t)n_rows * 12);

    adder12_kernel<<<blocks, ROWS_PER_BLOCK>>>(A4, B4, S4, Cout);
}